// round 8
// baseline (speedup 1.0000x reference)
#include <cuda_runtime.h>
#include <cuda_bf16.h>
#include <cstdint>

#define NN 50000
#define EE 800000
#define CH 256

// ---- scratch (device globals; no allocation allowed) ----
__device__ __align__(16) float g_xw[(size_t)NN * CH];      // x @ W (51.2 MB)
__device__ int   g_deg[NN];
__device__ int   g_off[NN + 1];
__device__ int   g_cur[NN];
__device__ __align__(16) int2 g_epack[EE];                 // (src, val) per edge
__device__ __align__(16) __nv_bfloat16 g_wthi[CH * CH];    // W^T hi [n][k]
__device__ __align__(16) __nv_bfloat16 g_wtlo[CH * CH];    // W^T lo [n][k]

// =============================================================== helpers
__device__ __forceinline__ uint32_t smem_u32(const void* p) {
    uint32_t a;
    asm("{ .reg .u64 t; cvta.to.shared.u64 t, %1; cvt.u32.u64 %0, t; }"
        : "=r"(a) : "l"(p));
    return a;
}

__device__ __forceinline__ void cp_async16(uint32_t s, const void* g) {
    asm volatile("cp.async.cg.shared.global [%0], [%1], 16;" :: "r"(s), "l"(g));
}
// src-size variant: sz==0 -> pure zero-fill (no global read of valid bytes)
__device__ __forceinline__ void cp_async16z(uint32_t s, const void* g, unsigned sz) {
    asm volatile("cp.async.cg.shared.global [%0], [%1], 16, %2;"
                 :: "r"(s), "l"(g), "r"(sz));
}
__device__ __forceinline__ void cp_commit() {
    asm volatile("cp.async.commit_group;" ::: "memory");
}
template <int N>
__device__ __forceinline__ void cp_wait() {
    asm volatile("cp.async.wait_group %0;" :: "n"(N) : "memory");
}

__device__ __forceinline__ void ldsm_x4(uint32_t* r, uint32_t addr) {
    asm volatile("ldmatrix.sync.aligned.m8n8.x4.shared.b16 {%0,%1,%2,%3}, [%4];"
                 : "=r"(r[0]), "=r"(r[1]), "=r"(r[2]), "=r"(r[3]) : "r"(addr));
}

// D(fp32) += A(bf16) * B(bf16), m16n8k16, A row-major frag, B col-major frag
__device__ __forceinline__ void mma_bf16(float* c, const uint32_t* a, const uint32_t* b) {
    asm volatile(
        "mma.sync.aligned.m16n8k16.row.col.f32.bf16.bf16.f32 "
        "{%0,%1,%2,%3}, {%4,%5,%6,%7}, {%8,%9}, {%0,%1,%2,%3};"
        : "+f"(c[0]), "+f"(c[1]), "+f"(c[2]), "+f"(c[3])
        : "r"(a[0]), "r"(a[1]), "r"(a[2]), "r"(a[3]), "r"(b[0]), "r"(b[1]));
}

// =============================================================== CSR build
__global__ void hist_kernel(const int* __restrict__ dst, int E) {
    int i = blockIdx.x * blockDim.x + threadIdx.x;
    if (i < E) atomicAdd(&g_deg[dst[i]], 1);
}

// single-pass SMEM scan: 1024 threads x 49 elements each (50176 >= NN)
#define SCAN_PER_T 49
#define SCAN_PAD   (1024 * SCAN_PER_T)           // 50176
#define SCAN_SMEM  (SCAN_PAD * 4)                // 200704 B

__global__ __launch_bounds__(1024) void scan_smem_kernel(int E) {
    extern __shared__ int sd[];
    __shared__ int wsum[32];
    int tid = threadIdx.x, lane = tid & 31, warp = tid >> 5;

    for (int i = tid; i < SCAN_PAD; i += 1024)
        sd[i] = (i < NN) ? g_deg[i] : 0;
    __syncthreads();

    int base = tid * SCAN_PER_T;
    int local = 0;
    for (int j = 0; j < SCAN_PER_T; j++) local += sd[base + j];

    // block exclusive scan of per-thread totals
    int x = local;
    #pragma unroll
    for (int o = 1; o < 32; o <<= 1) {
        int y = __shfl_up_sync(0xffffffffu, x, o);
        if (lane >= o) x += y;
    }
    if (lane == 31) wsum[warp] = x;
    __syncthreads();
    if (warp == 0) {
        int t = wsum[lane];
        #pragma unroll
        for (int o = 1; o < 32; o <<= 1) {
            int y = __shfl_up_sync(0xffffffffu, t, o);
            if (lane >= o) t += y;
        }
        wsum[lane] = t;
    }
    __syncthreads();
    int run = x - local + (warp > 0 ? wsum[warp - 1] : 0);

    for (int j = 0; j < SCAN_PER_T; j++) {
        int v = sd[base + j];
        sd[base + j] = run;
        run += v;
    }
    __syncthreads();
    for (int i = tid; i < NN; i += 1024) {
        int v = sd[i];
        g_off[i] = v;
        g_cur[i] = v;
    }
    if (tid == 0) g_off[NN] = E;
}

__global__ void scatter_kernel(const int* __restrict__ src,
                               const int* __restrict__ dst,
                               const float* __restrict__ val, int E) {
    int i = blockIdx.x * blockDim.x + threadIdx.x;
    if (i < E) {
        int p = atomicAdd(&g_cur[dst[i]], 1);
        g_epack[p] = make_int2(src[i], __float_as_int(val[i]));
    }
}

// =============================================================== W^T split
__global__ void split_wt_kernel(const float* __restrict__ W) {
    int k = threadIdx.x;
    int n = blockIdx.x;
    float w = W[k * CH + n];
    __nv_bfloat16 h = __float2bfloat16(w);
    g_wthi[n * CH + k] = h;
    g_wtlo[n * CH + k] = __float2bfloat16(w - __bfloat162float(h));
}

// =============================================================== fused GEMM
// g_xw[M, bn..bn+127] = x @ W[:, bn..bn+127] via split-bf16
// (D += AhiBhi + AhiBlo + AloBhi, fp32 accum). The x hi/lo split happens
// IN-KERNEL: cp.async fp32 x tile -> SMEM staging -> convert to bf16 hi/lo
// tiles (no g_xhi/g_xlo arrays, no split_x launch, no pad kernel).
// Per buffer (48 KB): AF32 16K | AHI 8K | ALO 8K | BHI 8K | BLO 8K; x2 = 96 KB.
#define SWZ(r, c) ((uint32_t)((r) * 64 + (((c) ^ ((r) & 3)) * 16)))
#define BUF_STRIDE 49152
#define OFF_AHI 16384
#define OFF_ALO 24576
#define OFF_BHI 32768
#define OFF_BLO 40960
#define GEMM_SMEM (2 * BUF_STRIDE)   // 98304

__global__ __launch_bounds__(256, 2) void gemm_mma(const float* __restrict__ x,
                                                   int M, int bn) {
    extern __shared__ char smem[];
    const uint32_t sb = smem_u32(smem);
    const int tid  = threadIdx.x;
    const int lane = tid & 31;
    const int wid  = tid >> 5;
    const int warp_m = (wid & 3) * 32;   // 0,32,64,96
    const int warp_n = (wid >> 2) * 64;  // 0,64
    const size_t arow = (size_t)blockIdx.x * 128;

    float acc[2][8][4];
    #pragma unroll
    for (int mt = 0; mt < 2; mt++)
        #pragma unroll
        for (int nt = 0; nt < 8; nt++)
            #pragma unroll
            for (int j = 0; j < 4; j++) acc[mt][nt][j] = 0.f;

    // ---- fill: A fp32 staging (swizzled 128B rows) + B hi/lo bf16 tiles ----
    auto fill = [&](int buf, int ch) {
        const int k0 = ch * 32;
        const uint32_t base = sb + buf * BUF_STRIDE;
        #pragma unroll
        for (int i = 0; i < 4; i++) {
            int chunk = tid + i * 256;          // 0..1023
            int r = chunk >> 3, k8 = chunk & 7; // row, fp32 16B-chunk
            uint32_t so = (uint32_t)(r * 128 + ((k8 ^ (r & 7)) * 16));
            size_t grow = arow + r;
            bool ok = grow < (size_t)M;
            const float* gp = &x[(ok ? grow : 0) * CH + k0 + 4 * k8];
            cp_async16z(base + so, gp, ok ? 16u : 0u);
        }
        #pragma unroll
        for (int i = 0; i < 2; i++) {
            int chunk = tid + i * 256;          // 0..511
            int r = chunk >> 2, c = chunk & 3;
            uint32_t so = SWZ(r, c);
            size_t gb = (size_t)(bn + r) * CH + k0 + c * 8;
            cp_async16(base + OFF_BHI + so, &g_wthi[gb]);
            cp_async16(base + OFF_BLO + so, &g_wtlo[gb]);
        }
    };

    // ---- convert: fp32 staging -> bf16 hi/lo A tiles ----
    auto convert = [&](int buf) {
        char* b = smem + buf * BUF_STRIDE;
        #pragma unroll
        for (int i = 0; i < 2; i++) {
            int task = tid + i * 256;           // 0..511
            int r = task >> 2, c = task & 3;    // row, bf16 16B-chunk
            float4 f0 = *(const float4*)(b + r * 128 + (((2 * c)     ^ (r & 7)) * 16));
            float4 f1 = *(const float4*)(b + r * 128 + (((2 * c + 1) ^ (r & 7)) * 16));
            float f[8] = {f0.x, f0.y, f0.z, f0.w, f1.x, f1.y, f1.z, f1.w};
            union { __nv_bfloat16 h[8]; uint4 u; } H, L;
            #pragma unroll
            for (int j = 0; j < 8; j++) {
                H.h[j] = __float2bfloat16(f[j]);
                L.h[j] = __float2bfloat16(f[j] - __bfloat162float(H.h[j]));
            }
            uint32_t so = SWZ(r, c);
            *(uint4*)(b + OFF_AHI + so) = H.u;
            *(uint4*)(b + OFF_ALO + so) = L.u;
        }
    };

    auto compute = [&](int buf) {
        const uint32_t base = sb + buf * BUF_STRIDE;
        #pragma unroll
        for (int ks = 0; ks < 2; ks++) {
            uint32_t a_hi[2][4], a_lo[2][4];
            const int achunk = 2 * ks + (lane >> 4);
            #pragma unroll
            for (int mt = 0; mt < 2; mt++) {
                int r = warp_m + mt * 16 + (lane & 15);
                uint32_t ad = base + OFF_AHI + SWZ(r, achunk);
                ldsm_x4(a_hi[mt], ad);
                ldsm_x4(a_lo[mt], ad + 8192);
            }
            #pragma unroll
            for (int np = 0; np < 4; np++) {
                int nr = warp_n + np * 16 + (lane & 7) + ((lane & 16) ? 8 : 0);
                int bchunk = 2 * ks + ((lane >> 3) & 1);
                uint32_t bd = base + OFF_BHI + SWZ(nr, bchunk);
                uint32_t bhi[4], blo[4];
                ldsm_x4(bhi, bd);
                ldsm_x4(blo, bd + 8192);
                #pragma unroll
                for (int h = 0; h < 2; h++) {
                    int nt = np * 2 + h;
                    #pragma unroll
                    for (int mt = 0; mt < 2; mt++) {
                        mma_bf16(acc[mt][nt], a_hi[mt], &bhi[2 * h]);
                        mma_bf16(acc[mt][nt], a_hi[mt], &blo[2 * h]);
                        mma_bf16(acc[mt][nt], a_lo[mt], &bhi[2 * h]);
                    }
                }
            }
        }
    };

    fill(0, 0);
    cp_commit();
    #pragma unroll 1
    for (int ch = 0; ch < 8; ch++) {
        if (ch < 7) {
            fill((ch + 1) & 1, ch + 1);
            cp_commit();
            cp_wait<1>();
        } else {
            cp_wait<0>();
        }
        __syncthreads();
        convert(ch & 1);
        __syncthreads();
        compute(ch & 1);
        __syncthreads();
    }

    #pragma unroll
    for (int mt = 0; mt < 2; mt++) {
        size_t r0 = arow + warp_m + mt * 16 + (lane >> 2);
        #pragma unroll
        for (int nt = 0; nt < 8; nt++) {
            int gc = bn + warp_n + nt * 8 + 2 * (lane & 3);
            if (r0 < (size_t)M)
                *(float2*)&g_xw[r0 * CH + gc] =
                    make_float2(acc[mt][nt][0], acc[mt][nt][1]);
            if (r0 + 8 < (size_t)M)
                *(float2*)&g_xw[(r0 + 8) * CH + gc] =
                    make_float2(acc[mt][nt][2], acc[mt][nt][3]);
        }
    }
}

// =============================================================== gather
// out[d][c0+c] = b[c0+c] + sum_{edges to d} val * xw[src][c0+c]
// One 128-channel half per launch; 8 nodes per 256-thread block.
__global__ __launch_bounds__(256) void gather_half(const float* __restrict__ bias,
                                                   float* __restrict__ out, int c0) {
    int node = blockIdx.x * 8 + (threadIdx.x >> 5);
    if (node >= NN) return;
    int c = c0 + ((threadIdx.x & 31) << 2);
    int s = g_off[node], e = g_off[node + 1];
    float4 acc = *(const float4*)&bias[c];
    int j = s;
    for (; j + 4 <= e; j += 4) {
        int2 e0 = g_epack[j],     e1 = g_epack[j + 1];
        int2 e2 = g_epack[j + 2], e3 = g_epack[j + 3];
        float v0 = __int_as_float(e0.y), v1 = __int_as_float(e1.y);
        float v2 = __int_as_float(e2.y), v3 = __int_as_float(e3.y);
        float4 x0 = *(const float4*)&g_xw[(size_t)e0.x * CH + c];
        float4 x1 = *(const float4*)&g_xw[(size_t)e1.x * CH + c];
        float4 x2 = *(const float4*)&g_xw[(size_t)e2.x * CH + c];
        float4 x3 = *(const float4*)&g_xw[(size_t)e3.x * CH + c];
        acc.x += v0 * x0.x; acc.y += v0 * x0.y; acc.z += v0 * x0.z; acc.w += v0 * x0.w;
        acc.x += v1 * x1.x; acc.y += v1 * x1.y; acc.z += v1 * x1.z; acc.w += v1 * x1.w;
        acc.x += v2 * x2.x; acc.y += v2 * x2.y; acc.z += v2 * x2.z; acc.w += v2 * x2.w;
        acc.x += v3 * x3.x; acc.y += v3 * x3.y; acc.z += v3 * x3.z; acc.w += v3 * x3.w;
    }
    for (; j < e; ++j) {
        int2 ep = g_epack[j];
        float v = __int_as_float(ep.y);
        float4 x0 = *(const float4*)&g_xw[(size_t)ep.x * CH + c];
        acc.x += v * x0.x; acc.y += v * x0.y; acc.z += v * x0.z; acc.w += v * x0.w;
    }
    *(float4*)&out[(size_t)node * CH + c] = acc;
}

// =============================================================== launch
// DAG (captured with forked streams so branches overlap at replay):
//   main:  split_wt -> gemm(n=0..127) -> gemm(n=128..255)
//   sB:    memset(deg) -> hist -> scan -> scatter
//   sC:    [gemm0 && scatter] -> gather cols 0..127
//   main:  [gemm1 && scatter] -> gather cols 128..255 -> join sC
extern "C" void kernel_launch(void* const* d_in, const int* in_sizes, int n_in,
                              void* d_out, int out_size) {
    const float* x    = (const float*)d_in[0];   // [N, 256]
    const float* W    = (const float*)d_in[1];   // [256, 256]
    const float* bias = (const float*)d_in[2];   // [256]
    const int*   esrc = (const int*)d_in[3];     // [E]
    const int*   edst = (const int*)d_in[4];     // [E]
    const float* eval = (const float*)d_in[5];   // [E]
    float* out = (float*)d_out;

    int M = in_sizes[0] / CH;   // 50000
    int E = in_sizes[3];        // 800000

    cudaFuncSetAttribute(gemm_mma, cudaFuncAttributeMaxDynamicSharedMemorySize,
                         GEMM_SMEM);
    cudaFuncSetAttribute(scan_smem_kernel,
                         cudaFuncAttributeMaxDynamicSharedMemorySize, SCAN_SMEM);

    cudaStream_t sB, sC;
    cudaStreamCreateWithFlags(&sB, cudaStreamNonBlocking);
    cudaStreamCreateWithFlags(&sC, cudaStreamNonBlocking);
    cudaEvent_t evRoot, evS, evG0, evC;
    cudaEventCreateWithFlags(&evRoot, cudaEventDisableTiming);
    cudaEventCreateWithFlags(&evS,    cudaEventDisableTiming);
    cudaEventCreateWithFlags(&evG0,   cudaEventDisableTiming);
    cudaEventCreateWithFlags(&evC,    cudaEventDisableTiming);

    // fork sB off the (captured) default stream
    cudaEventRecord(evRoot, 0);
    cudaStreamWaitEvent(sB, evRoot, 0);

    // ---- branch B: CSR-by-dst build ----
    void* degp = nullptr;
    cudaGetSymbolAddress(&degp, g_deg);
    cudaMemsetAsync(degp, 0, NN * sizeof(int), sB);
    hist_kernel<<<(E + 255) / 256, 256, 0, sB>>>(edst, E);
    scan_smem_kernel<<<1, 1024, SCAN_SMEM, sB>>>(E);
    scatter_kernel<<<(E + 255) / 256, 256, 0, sB>>>(esrc, edst, eval, E);
    cudaEventRecord(evS, sB);

    // ---- main branch: W split + fused GEMM halves ----
    split_wt_kernel<<<CH, CH>>>(W);
    int mblk = (M + 127) / 128;   // 391
    gemm_mma<<<mblk, 256, GEMM_SMEM>>>(x, M, 0);
    cudaEventRecord(evG0, 0);
    gemm_mma<<<mblk, 256, GEMM_SMEM>>>(x, M, 128);

    // ---- branch C: gather cols 0..127 (overlaps gemm half 1) ----
    cudaStreamWaitEvent(sC, evG0, 0);
    cudaStreamWaitEvent(sC, evS, 0);
    gather_half<<<(NN + 7) / 8, 256, 0, sC>>>(bias, out, 0);
    cudaEventRecord(evC, sC);

    // ---- main branch: gather cols 128..255, then join everything ----
    cudaStreamWaitEvent(0, evS, 0);
    gather_half<<<(NN + 7) / 8, 256>>>(bias, out, 128);
    cudaStreamWaitEvent(0, evC, 0);

    cudaEventDestroy(evRoot);
    cudaEventDestroy(evS);
    cudaEventDestroy(evG0);
    cudaEventDestroy(evC);
    cudaStreamDestroy(sB);
    cudaStreamDestroy(sC);
}